// round 1
// baseline (speedup 1.0000x reference)
#include <cuda_runtime.h>
#include <math.h>

#define B_  4
#define T_  2048
#define C_  1024
#define H_  16
#define D_  64
#define C3_ 3072

// Scratch (allocation-free): qkv [B,T,3C], y [B,T,C]
__device__ float g_qkv[(size_t)B_ * T_ * C3_];
__device__ float g_y[(size_t)B_ * T_ * C_];

// ---------------------------------------------------------------------------
// Classic SGEMM: C[M,N] = A[M,K] @ B[K,N] + bias[N]
// 128x128 block tile, BK=8, 256 threads, 8x8 microtile. Requires
// M%128==0, N%128==0, K%8==0 (true for all our shapes).
// ---------------------------------------------------------------------------
__global__ __launch_bounds__(256) void sgemm_bias(
    const float* __restrict__ A, const float* __restrict__ Bm,
    const float* __restrict__ bias, float* __restrict__ C,
    int M, int N, int K)
{
    __shared__ float As[8][132];   // padded to dodge store conflicts
    __shared__ float Bs[8][128];

    const int tid  = threadIdx.x;
    const int arow = tid >> 1;          // 0..127
    const int acol = (tid & 1) << 2;    // 0 or 4
    const int brow = tid >> 5;          // 0..7
    const int bcol = (tid & 31) << 2;   // 0..124
    const int tx = tid & 15, ty = tid >> 4;

    const float* Ab = A  + (size_t)blockIdx.y * 128 * K;
    const float* Bb = Bm + (size_t)blockIdx.x * 128;

    float acc[8][8];
    #pragma unroll
    for (int i = 0; i < 8; i++)
        #pragma unroll
        for (int j = 0; j < 8; j++) acc[i][j] = 0.f;

    for (int k0 = 0; k0 < K; k0 += 8) {
        float4 a4 = *(const float4*)(Ab + (size_t)arow * K + k0 + acol);
        As[acol + 0][arow] = a4.x;
        As[acol + 1][arow] = a4.y;
        As[acol + 2][arow] = a4.z;
        As[acol + 3][arow] = a4.w;
        float4 b4 = *(const float4*)(Bb + (size_t)(k0 + brow) * N + bcol);
        *(float4*)&Bs[brow][bcol] = b4;
        __syncthreads();

        #pragma unroll
        for (int kk = 0; kk < 8; kk++) {
            float ar[8], br[8];
            *(float4*)&ar[0] = *(const float4*)&As[kk][ty * 8];
            *(float4*)&ar[4] = *(const float4*)&As[kk][ty * 8 + 4];
            *(float4*)&br[0] = *(const float4*)&Bs[kk][tx * 8];
            *(float4*)&br[4] = *(const float4*)&Bs[kk][tx * 8 + 4];
            #pragma unroll
            for (int i = 0; i < 8; i++)
                #pragma unroll
                for (int j = 0; j < 8; j++)
                    acc[i][j] += ar[i] * br[j];
        }
        __syncthreads();
    }

    #pragma unroll
    for (int i = 0; i < 8; i++) {
        size_t row = (size_t)blockIdx.y * 128 + ty * 8 + i;
        #pragma unroll
        for (int j = 0; j < 8; j += 4) {
            int col = blockIdx.x * 128 + tx * 8 + j;
            float4 o;
            o.x = acc[i][j + 0] + bias[col + 0];
            o.y = acc[i][j + 1] + bias[col + 1];
            o.z = acc[i][j + 2] + bias[col + 2];
            o.w = acc[i][j + 3] + bias[col + 3];
            *(float4*)(C + row * N + col) = o;
        }
    }
}

// ---------------------------------------------------------------------------
// Sparsemax over the head dim (64) of K, in-place inside g_qkv.
// Rows = (b,t,h), 131072 total. 64 threads (2 warps) per row, 4 rows/block.
// O(d^2) rank/sum formulation (no sort): for each element compute its
// descending rank + prefix sum of all >= it, then rho/tau exactly as in the
// reference (ties broken by index; random fp32 data won't tie anyway).
// ---------------------------------------------------------------------------
__global__ __launch_bounds__(256) void sparsemax_k(float* __restrict__ qkv)
{
    __shared__ float zb[4][64];
    __shared__ int   cnt2[4][2];
    __shared__ float sum2[4][2];

    const int tid  = threadIdx.x;
    const int r    = tid >> 6;          // row within block
    const int lane = tid & 63;
    const size_t row = (size_t)blockIdx.x * 4 + r;   // (b*T+t)*H + h
    const size_t bt  = row >> 4;                      // / H
    const int    h   = (int)(row & 15);

    float* p = qkv + bt * C3_ + C_ + h * D_ + lane;
    float z = *p;
    zb[r][lane] = z;
    __syncthreads();

    float sumge = 0.f; int rank = 0;
    #pragma unroll
    for (int j = 0; j < 64; j++) {
        float zj = zb[r][j];
        bool ge = (zj > z) || (zj == z && j <= lane);
        sumge += ge ? zj : 0.f;
        rank  += ge ? 1 : 0;
    }
    int c = (1.f + (float)rank * z > sumge) ? 1 : 0;
    #pragma unroll
    for (int o = 16; o > 0; o >>= 1) c += __shfl_xor_sync(0xffffffffu, c, o);
    if ((tid & 31) == 0) cnt2[r][lane >> 5] = c;
    __syncthreads();
    int rho = cnt2[r][0] + cnt2[r][1];

    float zs = (rank <= rho) ? z : 0.f;
    #pragma unroll
    for (int o = 16; o > 0; o >>= 1) zs += __shfl_xor_sync(0xffffffffu, zs, o);
    if ((tid & 31) == 0) sum2[r][lane >> 5] = zs;
    __syncthreads();
    float cs  = sum2[r][0] + sum2[r][1];
    float tau = (cs - 1.f) / (float)rho;
    *p = fmaxf(z - tau, 0.f);
}

// ---------------------------------------------------------------------------
// Flash attention (causal, online softmax) + fused XSA output correction.
// Grid (T/128, H, B), 128 threads; thread owns one q row (q + O in regs).
// K/V tiles of 64 rows in smem, read as broadcast float4 (1 LDS per 4 FMA).
// Writes y in [B,T,C] layout for the projection GEMM.
// ---------------------------------------------------------------------------
__global__ __launch_bounds__(128) void flash_xsa(
    const float* __restrict__ qkv, float* __restrict__ y)
{
    __shared__ float4 ks[64][16];
    __shared__ float4 vs[64][16];

    const int b = blockIdx.z, h = blockIdx.y;
    const int tq = blockIdx.x * 128 + threadIdx.x;
    const size_t base = (size_t)b * T_ * C3_;

    float q[64];
    {
        const float* qrow = qkv + base + (size_t)tq * C3_ + h * D_;
        #pragma unroll
        for (int dd = 0; dd < 16; dd++) {
            float4 t4 = *(const float4*)(qrow + dd * 4);
            q[dd*4+0] = t4.x; q[dd*4+1] = t4.y; q[dd*4+2] = t4.z; q[dd*4+3] = t4.w;
        }
    }

    float O[64];
    #pragma unroll
    for (int d = 0; d < 64; d++) O[d] = 0.f;
    float m = -1e30f, l = 0.f;

    const int ktiles = (blockIdx.x + 1) * 2;   // tiles covering causal range
    for (int kt = 0; kt < ktiles; kt++) {
        for (int i = threadIdx.x; i < 1024; i += 128) {
            int j = i >> 4, dd = i & 15;
            const float* kvp = qkv + base + (size_t)(kt * 64 + j) * C3_ + h * D_ + dd * 4;
            ks[j][dd] = *(const float4*)(kvp + C_);
            vs[j][dd] = *(const float4*)(kvp + 2 * C_);
        }
        __syncthreads();

        const int jlim = tq - kt * 64;   // valid kv index j <= jlim
        if (jlim >= 0) {
            for (int j0 = 0; j0 < 64 && j0 <= jlim; j0 += 16) {
                float s[16], cmax = -1e30f;
                #pragma unroll
                for (int jj = 0; jj < 16; jj++) {
                    int j = j0 + jj;
                    float acc = 0.f;
                    #pragma unroll
                    for (int dd = 0; dd < 16; dd++) {
                        float4 k4 = ks[j][dd];
                        acc += q[dd*4+0] * k4.x;
                        acc += q[dd*4+1] * k4.y;
                        acc += q[dd*4+2] * k4.z;
                        acc += q[dd*4+3] * k4.w;
                    }
                    s[jj] = (j <= jlim) ? acc * 0.125f : -1e30f;
                    cmax = fmaxf(cmax, s[jj]);
                }
                float mnew = fmaxf(m, cmax);
                float corr = __expf(m - mnew);
                l *= corr;
                #pragma unroll
                for (int d = 0; d < 64; d++) O[d] *= corr;
                #pragma unroll
                for (int jj = 0; jj < 16; jj++) {
                    float p = __expf(s[jj] - mnew);
                    l += p;
                    int j = j0 + jj;
                    #pragma unroll
                    for (int dd = 0; dd < 16; dd++) {
                        float4 v4 = vs[j][dd];
                        O[dd*4+0] += p * v4.x;
                        O[dd*4+1] += p * v4.y;
                        O[dd*4+2] += p * v4.z;
                        O[dd*4+3] += p * v4.w;
                    }
                }
                m = mnew;
            }
        }
        __syncthreads();
    }

    // finalize softmax + XSA correction: y -= (y . v_hat) v_hat
    float invl = 1.f / l;
    float vr[64];
    const float* vrow = qkv + base + (size_t)tq * C3_ + 2 * C_ + h * D_;
    #pragma unroll
    for (int dd = 0; dd < 16; dd++) {
        float4 v4 = *(const float4*)(vrow + dd * 4);
        vr[dd*4+0] = v4.x; vr[dd*4+1] = v4.y; vr[dd*4+2] = v4.z; vr[dd*4+3] = v4.w;
    }
    float vn = 0.f;
    #pragma unroll
    for (int d = 0; d < 64; d++) { O[d] *= invl; vn += vr[d] * vr[d]; }
    float inv_norm = 1.f / fmaxf(sqrtf(vn), 1e-12f);
    float coef = 0.f;
    #pragma unroll
    for (int d = 0; d < 64; d++) coef += O[d] * vr[d];
    coef *= inv_norm * inv_norm;   // (y . v_hat) / norm

    float* yout = y + ((size_t)(b * T_ + tq)) * C_ + h * D_;
    #pragma unroll
    for (int dd = 0; dd < 16; dd++) {
        float4 o4;
        o4.x = O[dd*4+0] - coef * vr[dd*4+0];
        o4.y = O[dd*4+1] - coef * vr[dd*4+1];
        o4.z = O[dd*4+2] - coef * vr[dd*4+2];
        o4.w = O[dd*4+3] - coef * vr[dd*4+3];
        *(float4*)(yout + dd * 4) = o4;
    }
}

// ---------------------------------------------------------------------------
extern "C" void kernel_launch(void* const* d_in, const int* in_sizes, int n_in,
                              void* d_out, int out_size)
{
    const float* x  = (const float*)d_in[0];
    const float* Wa = (const float*)d_in[1];
    const float* ba = (const float*)d_in[2];
    const float* Wp = (const float*)d_in[3];
    const float* bp = (const float*)d_in[4];
    float* out = (float*)d_out;

    float *qkv, *yb;
    cudaGetSymbolAddress((void**)&qkv, g_qkv);
    cudaGetSymbolAddress((void**)&yb,  g_y);

    // 1) qkv = x @ W_attn + b_attn   [8192,1024] x [1024,3072]
    {
        dim3 grid(C3_ / 128, (B_ * T_) / 128);
        sgemm_bias<<<grid, 256>>>(x, Wa, ba, qkv, B_ * T_, C3_, C_);
    }
    // 2) sparsemax over head dim of K (in place)
    sparsemax_k<<<(B_ * T_ * H_) / 4, 256>>>(qkv);
    // 3) flash attention + XSA correction -> y [B,T,C]
    {
        dim3 grid(T_ / 128, H_, B_);
        flash_xsa<<<grid, 128>>>(qkv, yb);
    }
    // 4) out = y @ W_proj + b_proj   [8192,1024] x [1024,1024]
    {
        dim3 grid(C_ / 128, (B_ * T_) / 128);
        sgemm_bias<<<grid, 256>>>(yb, Wp, bp, out, B_ * T_, C_, C_);
    }
}